// round 3
// baseline (speedup 1.0000x reference)
#include <cuda_runtime.h>
#include <cuda_bf16.h>
#include <math.h>

#define N_NODES 50000
#define E_EDGES 1600000
#define HID 256
#define F_IN 128
#define NB 64
#define NC 10

// ---------------- static device scratch ----------------
__device__ float d_agg[(size_t)N_NODES * HID];
__device__ float d_h1[(size_t)N_NODES * HID];
__device__ float d_h2[(size_t)N_NODES * HID];
__device__ int   d_deg[N_NODES];
__device__ float d_invdeg[N_NODES];
__device__ int   d_rowptr[N_NODES + 1];
__device__ int   d_cursor[N_NODES];
__device__ int   d_srcs[E_EDGES];
__device__ float d_gate[N_NODES];
__device__ int   d_bstart[NB + 1];
__device__ float d_pooled[NB * HID];

// ---------------- zero degree array (memset not capture-safe on __device__ mem) ----------------
__global__ void zero_deg_kernel() {
    int i = blockIdx.x * blockDim.x + threadIdx.x;
    if (i < N_NODES) d_deg[i] = 0;
}

// ---------------- CSR build (edge_index is int32: JAX x64 disabled) ----------------
__global__ void hist_kernel(const int* __restrict__ ei) {
    int e = blockIdx.x * blockDim.x + threadIdx.x;
    if (e >= E_EDGES) return;
    int dst = ei[E_EDGES + e];
    if ((unsigned)dst < (unsigned)N_NODES) atomicAdd(&d_deg[dst], 1);
}

__global__ void scan_kernel(int n) {
    __shared__ int sd[1024];
    int tid = threadIdx.x;
    int run = 0;
    for (int base = 0; base < n; base += 1024) {
        int idx = base + tid;
        int v = (idx < n) ? d_deg[idx] : 0;
        sd[tid] = v;
        __syncthreads();
        for (int off = 1; off < 1024; off <<= 1) {
            int t = (tid >= off) ? sd[tid - off] : 0;
            __syncthreads();
            sd[tid] += t;
            __syncthreads();
        }
        if (idx < n) {
            int excl = run + sd[tid] - v;
            d_rowptr[idx] = excl;
            d_cursor[idx] = excl;
            d_invdeg[idx] = 1.0f / (float)max(v, 1);
        }
        run += sd[1023];
        __syncthreads();
    }
    if (tid == 0) d_rowptr[n] = run;
}

__global__ void fill_kernel(const int* __restrict__ ei) {
    int e = blockIdx.x * blockDim.x + threadIdx.x;
    if (e >= E_EDGES) return;
    int src = ei[e];
    int dst = ei[E_EDGES + e];
    if ((unsigned)dst >= (unsigned)N_NODES || (unsigned)src >= (unsigned)N_NODES) return;
    int pos = atomicAdd(&d_cursor[dst], 1);
    d_srcs[pos] = src;
}

// ---------------- aggregation (mean over neighbors) ----------------
// one block per dst node, blockDim = feature width K
__global__ void aggregate_kernel(const float* __restrict__ xin, float* __restrict__ agg, int K) {
    int n = blockIdx.x;
    int t = threadIdx.x;
    int beg = d_rowptr[n], end = d_rowptr[n + 1];
    __shared__ int sidx[256];
    float a0 = 0.f, a1 = 0.f, a2 = 0.f, a3 = 0.f;
    for (int base = beg; base < end; base += blockDim.x) {
        int cnt = min((int)blockDim.x, end - base);
        if (t < cnt) sidx[t] = d_srcs[base + t];
        __syncthreads();
        int i = 0;
        for (; i + 4 <= cnt; i += 4) {
            a0 += xin[(size_t)sidx[i] * K + t];
            a1 += xin[(size_t)sidx[i + 1] * K + t];
            a2 += xin[(size_t)sidx[i + 2] * K + t];
            a3 += xin[(size_t)sidx[i + 3] * K + t];
        }
        for (; i < cnt; i++) a0 += xin[(size_t)sidx[i] * K + t];
        __syncthreads();
    }
    agg[(size_t)n * K + t] = (a0 + a1 + a2 + a3) * d_invdeg[n];
}

// ---------------- TF32 tensor-core fused SAGE linear ----------------
// out[n,j] = relu( bias[j] + sum_k A0[n,k]*W0[j,k] + sum_k A1[n,k]*W1[j,k] )
__device__ __forceinline__ unsigned f2tf32(float f) {
    unsigned u;
    asm("cvt.rna.tf32.f32 %0, %1;" : "=r"(u) : "f"(f));
    return u;
}

__device__ __forceinline__ void mma_tf32(float c[4], const unsigned a[4], const unsigned b[2]) {
    asm volatile(
        "mma.sync.aligned.m16n8k8.row.col.f32.tf32.tf32.f32 "
        "{%0,%1,%2,%3}, {%4,%5,%6,%7}, {%8,%9}, {%0,%1,%2,%3};"
        : "+f"(c[0]), "+f"(c[1]), "+f"(c[2]), "+f"(c[3])
        : "r"(a[0]), "r"(a[1]), "r"(a[2]), "r"(a[3]), "r"(b[0]), "r"(b[1]));
}

__global__ __launch_bounds__(256) void sage_linear_kernel(
    const float* __restrict__ A0, const float* __restrict__ A1,
    const float* __restrict__ W0, const float* __restrict__ W1,
    const float* __restrict__ bias, float* __restrict__ out,
    int M, int Ka)
{
    __shared__ float As[128][36];
    __shared__ float Ws[64][36];
    int tid = threadIdx.x;
    int wid = tid >> 5, lane = tid & 31;
    int wm = wid & 3, wn = wid >> 2;            // 4 x 2 warp grid, each 32x32
    int g = lane >> 2, tg = lane & 3;
    int bm = blockIdx.x, bn = blockIdx.y;

    float c[2][4][4];
#pragma unroll
    for (int i = 0; i < 2; i++)
#pragma unroll
        for (int j = 0; j < 4; j++)
#pragma unroll
            for (int k = 0; k < 4; k++) c[i][j][k] = 0.f;

#pragma unroll
    for (int part = 0; part < 2; part++) {
        const float* Asrc = part ? A1 : A0;
        const float* Wsrc = part ? W1 : W0;
        for (int kb = 0; kb < Ka; kb += 32) {
            // A tile: 128 rows x 32 k
#pragma unroll
            for (int i = 0; i < 4; i++) {
                int l = tid + i * 256;
                int row = l >> 3, c4 = l & 7;
                int gr = bm * 128 + row;
                float4 v = make_float4(0.f, 0.f, 0.f, 0.f);
                if (gr < M) v = *reinterpret_cast<const float4*>(Asrc + (size_t)gr * Ka + kb + c4 * 4);
                *reinterpret_cast<float4*>(&As[row][c4 * 4]) = v;
            }
            // W tile: 64 rows(j) x 32 k
#pragma unroll
            for (int i = 0; i < 2; i++) {
                int l = tid + i * 256;
                int row = l >> 3, c4 = l & 7;
                int gj = bn * 64 + row;
                float4 v = *reinterpret_cast<const float4*>(Wsrc + (size_t)gj * Ka + kb + c4 * 4);
                *reinterpret_cast<float4*>(&Ws[row][c4 * 4]) = v;
            }
            __syncthreads();
#pragma unroll
            for (int kk = 0; kk < 32; kk += 8) {
                unsigned a[2][4], bf[4][2];
#pragma unroll
                for (int mi = 0; mi < 2; mi++) {
                    int rm = wm * 32 + mi * 16;
                    a[mi][0] = f2tf32(As[rm + g][kk + tg]);
                    a[mi][1] = f2tf32(As[rm + g + 8][kk + tg]);
                    a[mi][2] = f2tf32(As[rm + g][kk + tg + 4]);
                    a[mi][3] = f2tf32(As[rm + g + 8][kk + tg + 4]);
                }
#pragma unroll
                for (int ni = 0; ni < 4; ni++) {
                    int jn = wn * 32 + ni * 8 + g;
                    bf[ni][0] = f2tf32(Ws[jn][kk + tg]);
                    bf[ni][1] = f2tf32(Ws[jn][kk + tg + 4]);
                }
#pragma unroll
                for (int mi = 0; mi < 2; mi++)
#pragma unroll
                    for (int ni = 0; ni < 4; ni++)
                        mma_tf32(c[mi][ni], a[mi], bf[ni]);
            }
            __syncthreads();
        }
    }

    // epilogue: bias + relu + store
#pragma unroll
    for (int mi = 0; mi < 2; mi++) {
        int row0 = bm * 128 + wm * 32 + mi * 16 + g;
        int row1 = row0 + 8;
#pragma unroll
        for (int ni = 0; ni < 4; ni++) {
            int col = bn * 64 + wn * 32 + ni * 8 + 2 * tg;
            float b0 = bias[col], b1v = bias[col + 1];
            float v00 = fmaxf(c[mi][ni][0] + b0, 0.f);
            float v01 = fmaxf(c[mi][ni][1] + b1v, 0.f);
            float v10 = fmaxf(c[mi][ni][2] + b0, 0.f);
            float v11 = fmaxf(c[mi][ni][3] + b1v, 0.f);
            if (row0 < M) { out[(size_t)row0 * HID + col] = v00; out[(size_t)row0 * HID + col + 1] = v01; }
            if (row1 < M) { out[(size_t)row1 * HID + col] = v10; out[(size_t)row1 * HID + col + 1] = v11; }
        }
    }
}

// ---------------- gate: gate[n] = h[n,:] . Wg + bg ----------------
__global__ void gate_kernel(const float* __restrict__ h, const float* __restrict__ Wg,
                            const float* __restrict__ bg, float* __restrict__ gate) {
    int gw = (blockIdx.x * blockDim.x + threadIdx.x) >> 5;
    int lane = threadIdx.x & 31;
    int nw = (gridDim.x * blockDim.x) >> 5;
    for (int n = gw; n < N_NODES; n += nw) {
        float s = 0.f;
#pragma unroll
        for (int k = lane; k < HID; k += 32) s += h[(size_t)n * HID + k] * Wg[k];
#pragma unroll
        for (int o = 16; o > 0; o >>= 1) s += __shfl_xor_sync(0xffffffff, s, o);
        if (lane == 0) gate[n] = s + bg[0];
    }
}

// ---------------- batch segment bounds (batch sorted, int32) ----------------
__global__ void batch_bounds_kernel(const int* __restrict__ batch) {
    int b = threadIdx.x;
    if (b > NB) return;
    if (b == NB) { d_bstart[NB] = N_NODES; return; }
    int lo = 0, hi = N_NODES;
    while (lo < hi) {
        int mid = (lo + hi) >> 1;
        if (batch[mid] < b) lo = mid + 1; else hi = mid;
    }
    d_bstart[b] = lo;
}

// ---------------- attention pool: one block per batch ----------------
__global__ void pool_kernel(const float* __restrict__ h, const float* __restrict__ gate,
                            float* __restrict__ pooled) {
    int b = blockIdx.x, tid = threadIdx.x;
    int beg = d_bstart[b], end = d_bstart[b + 1];
    __shared__ float red[256];
    __shared__ float se[256];

    float m = -3.4e38f;
    for (int n = beg + tid; n < end; n += 256) m = fmaxf(m, gate[n]);
    red[tid] = m; __syncthreads();
    for (int o = 128; o > 0; o >>= 1) { if (tid < o) red[tid] = fmaxf(red[tid], red[tid + o]); __syncthreads(); }
    float mx = red[0]; __syncthreads();

    float s = 0.f;
    for (int n = beg + tid; n < end; n += 256) s += expf(gate[n] - mx);
    red[tid] = s; __syncthreads();
    for (int o = 128; o > 0; o >>= 1) { if (tid < o) red[tid] += red[tid + o]; __syncthreads(); }
    float ssum = red[0]; __syncthreads();

    float acc = 0.f;
    for (int base = beg; base < end; base += 256) {
        int cnt = min(256, end - base);
        if (tid < cnt) se[tid] = expf(gate[base + tid] - mx);
        __syncthreads();
        for (int i = 0; i < cnt; i++) acc += se[i] * h[(size_t)(base + i) * HID + tid];
        __syncthreads();
    }
    pooled[b * HID + tid] = (end > beg) ? acc / ssum : 0.f;
}

// ---------------- MLP head + log_softmax: one block per batch ----------------
__global__ void head_kernel(const float* __restrict__ pooled,
                            const float* __restrict__ W1, const float* __restrict__ b1,
                            const float* __restrict__ W2, const float* __restrict__ b2,
                            float* __restrict__ out) {
    int b = blockIdx.x, t = threadIdx.x;
    __shared__ float pin[HID], m1[HID];
    __shared__ float logits[NC];
    pin[t] = pooled[b * HID + t];
    __syncthreads();
    float acc = b1[t];
#pragma unroll 8
    for (int k = 0; k < HID; k++) acc += pin[k] * W1[t * HID + k];
    m1[t] = fmaxf(acc, 0.f);
    __syncthreads();
    if (t < NC) {
        float a = b2[t];
        for (int k = 0; k < HID; k++) a += m1[k] * W2[t * HID + k];
        logits[t] = a;
    }
    __syncthreads();
    if (t == 0) {
        float mx = logits[0];
        for (int c2 = 1; c2 < NC; c2++) mx = fmaxf(mx, logits[c2]);
        float s = 0.f;
        for (int c2 = 0; c2 < NC; c2++) s += expf(logits[c2] - mx);
        float lse = mx + logf(s);
        for (int c2 = 0; c2 < NC; c2++) out[b * NC + c2] = logits[c2] - lse;
    }
}

// ---------------- launch ----------------
extern "C" void kernel_launch(void* const* d_in, const int* in_sizes, int n_in,
                              void* d_out, int out_size) {
    const float* x      = (const float*)d_in[0];
    const int* ei       = (const int*)d_in[1];     // int32 (JAX x64 disabled)
    const int* batch    = (const int*)d_in[2];     // int32
    const float* W1l = (const float*)d_in[3];
    const float* b1l = (const float*)d_in[4];
    const float* W1r = (const float*)d_in[5];
    const float* W2l = (const float*)d_in[6];
    const float* b2l = (const float*)d_in[7];
    const float* W2r = (const float*)d_in[8];
    const float* W3l = (const float*)d_in[9];
    const float* b3l = (const float*)d_in[10];
    const float* W3r = (const float*)d_in[11];
    const float* Wg  = (const float*)d_in[12];
    const float* bg  = (const float*)d_in[13];
    const float* Wl1 = (const float*)d_in[14];
    const float* bl1 = (const float*)d_in[15];
    const float* Wl2 = (const float*)d_in[16];
    const float* bl2 = (const float*)d_in[17];
    float* out = (float*)d_out;

    void *p_agg_, *p_h1_, *p_h2_, *p_gate_, *p_pooled_;
    cudaGetSymbolAddress(&p_agg_, d_agg);
    cudaGetSymbolAddress(&p_h1_, d_h1);
    cudaGetSymbolAddress(&p_h2_, d_h2);
    cudaGetSymbolAddress(&p_gate_, d_gate);
    cudaGetSymbolAddress(&p_pooled_, d_pooled);
    float* p_agg = (float*)p_agg_;
    float* p_h1 = (float*)p_h1_;
    float* p_h2 = (float*)p_h2_;
    float* p_gate = (float*)p_gate_;
    float* p_pooled = (float*)p_pooled_;

    const int eblocks = (E_EDGES + 255) / 256;

    // CSR build
    zero_deg_kernel<<<(N_NODES + 255) / 256, 256>>>();
    hist_kernel<<<eblocks, 256>>>(ei);
    scan_kernel<<<1, 1024>>>(N_NODES);
    fill_kernel<<<eblocks, 256>>>(ei);

    dim3 gemm_grid((N_NODES + 127) / 128, HID / 64);

    // layer 1 (Ka = 128)
    aggregate_kernel<<<N_NODES, F_IN>>>(x, p_agg, F_IN);
    sage_linear_kernel<<<gemm_grid, 256>>>(p_agg, x, W1l, W1r, b1l, p_h1, N_NODES, F_IN);
    // layer 2
    aggregate_kernel<<<N_NODES, HID>>>(p_h1, p_agg, HID);
    sage_linear_kernel<<<gemm_grid, 256>>>(p_agg, p_h1, W2l, W2r, b2l, p_h2, N_NODES, HID);
    // layer 3
    aggregate_kernel<<<N_NODES, HID>>>(p_h2, p_agg, HID);
    sage_linear_kernel<<<gemm_grid, 256>>>(p_agg, p_h2, W3l, W3r, b3l, p_h1, N_NODES, HID);

    // pooling + head
    gate_kernel<<<256, 256>>>(p_h1, Wg, bg, p_gate);
    batch_bounds_kernel<<<1, NB + 1>>>(batch);
    pool_kernel<<<NB, 256>>>(p_h1, p_gate, p_pooled);
    head_kernel<<<NB, HID>>>(p_pooled, Wl1, bl1, Wl2, bl2, out);
}

// round 4
// speedup vs baseline: 1.2921x; 1.2921x over previous
#include <cuda_runtime.h>
#include <cuda_bf16.h>
#include <math.h>

#define N_NODES 50000
#define E_EDGES 1600000
#define HID 256
#define F_IN 128
#define NB 64
#define NC 10

// ---------------- static device scratch ----------------
__device__ float d_agg[(size_t)N_NODES * HID];
__device__ float d_h1[(size_t)N_NODES * HID];
__device__ float d_h2[(size_t)N_NODES * HID];
__device__ int   d_deg[N_NODES];
__device__ float d_invdeg[N_NODES];
__device__ int   d_rowptr[N_NODES + 1];
__device__ int   d_cursor[N_NODES];
__device__ int   d_srcs[E_EDGES];
__device__ float d_gate[N_NODES];
__device__ int   d_bstart[NB + 1];
__device__ float d_pooled[NB * HID];
__device__ float d_pmax[NB];
__device__ float d_psum[NB];

// ---------------- zero degree array ----------------
__global__ void zero_deg_kernel() {
    int i = blockIdx.x * blockDim.x + threadIdx.x;
    if (i < N_NODES) d_deg[i] = 0;
}

// ---------------- CSR build (edge_index int32) ----------------
__global__ void hist_kernel(const int* __restrict__ ei) {
    int e = blockIdx.x * blockDim.x + threadIdx.x;
    if (e >= E_EDGES) return;
    int dst = ei[E_EDGES + e];
    if ((unsigned)dst < (unsigned)N_NODES) atomicAdd(&d_deg[dst], 1);
}

__global__ void scan_kernel(int n) {
    __shared__ int sd[1024];
    int tid = threadIdx.x;
    int run = 0;
    for (int base = 0; base < n; base += 1024) {
        int idx = base + tid;
        int v = (idx < n) ? d_deg[idx] : 0;
        sd[tid] = v;
        __syncthreads();
        for (int off = 1; off < 1024; off <<= 1) {
            int t = (tid >= off) ? sd[tid - off] : 0;
            __syncthreads();
            sd[tid] += t;
            __syncthreads();
        }
        if (idx < n) {
            int excl = run + sd[tid] - v;
            d_rowptr[idx] = excl;
            d_cursor[idx] = excl;
            d_invdeg[idx] = 1.0f / (float)max(v, 1);
        }
        run += sd[1023];
        __syncthreads();
    }
    if (tid == 0) d_rowptr[n] = run;
}

__global__ void fill_kernel(const int* __restrict__ ei) {
    int e = blockIdx.x * blockDim.x + threadIdx.x;
    if (e >= E_EDGES) return;
    int src = ei[e];
    int dst = ei[E_EDGES + e];
    if ((unsigned)dst >= (unsigned)N_NODES || (unsigned)src >= (unsigned)N_NODES) return;
    int pos = atomicAdd(&d_cursor[dst], 1);
    d_srcs[pos] = src;
}

// ---------------- vectorized aggregation (mean over neighbors) ----------------
// one block per dst node, blockDim = K/4 threads, float4 lanes
template <int K4>
__global__ __launch_bounds__(K4) void aggregate_kernel_v(const float* __restrict__ xin,
                                                          float* __restrict__ agg) {
    int n = blockIdx.x;
    int t = threadIdx.x;
    int beg = d_rowptr[n], end = d_rowptr[n + 1];
    const float4* __restrict__ x4 = reinterpret_cast<const float4*>(xin);
    __shared__ int sidx[K4];
    float4 a0 = make_float4(0.f, 0.f, 0.f, 0.f), a1 = a0, a2 = a0, a3 = a0;
    for (int base = beg; base < end; base += K4) {
        int cnt = min(K4, end - base);
        if (t < cnt) sidx[t] = d_srcs[base + t];
        __syncthreads();
        int i = 0;
        for (; i + 4 <= cnt; i += 4) {
            float4 v0 = x4[(size_t)sidx[i]     * K4 + t];
            float4 v1 = x4[(size_t)sidx[i + 1] * K4 + t];
            float4 v2 = x4[(size_t)sidx[i + 2] * K4 + t];
            float4 v3 = x4[(size_t)sidx[i + 3] * K4 + t];
            a0.x += v0.x; a0.y += v0.y; a0.z += v0.z; a0.w += v0.w;
            a1.x += v1.x; a1.y += v1.y; a1.z += v1.z; a1.w += v1.w;
            a2.x += v2.x; a2.y += v2.y; a2.z += v2.z; a2.w += v2.w;
            a3.x += v3.x; a3.y += v3.y; a3.z += v3.z; a3.w += v3.w;
        }
        for (; i < cnt; i++) {
            float4 v = x4[(size_t)sidx[i] * K4 + t];
            a0.x += v.x; a0.y += v.y; a0.z += v.z; a0.w += v.w;
        }
        __syncthreads();
    }
    float inv = d_invdeg[n];
    float4 r;
    r.x = (a0.x + a1.x + a2.x + a3.x) * inv;
    r.y = (a0.y + a1.y + a2.y + a3.y) * inv;
    r.z = (a0.z + a1.z + a2.z + a3.z) * inv;
    r.w = (a0.w + a1.w + a2.w + a3.w) * inv;
    reinterpret_cast<float4*>(agg)[(size_t)n * K4 + t] = r;
}

// ---------------- TF32 tensor-core fused SAGE linear ----------------
__device__ __forceinline__ unsigned f2tf32(float f) {
    unsigned u;
    asm("cvt.rna.tf32.f32 %0, %1;" : "=r"(u) : "f"(f));
    return u;
}

__device__ __forceinline__ void mma_tf32(float c[4], const unsigned a[4], const unsigned b[2]) {
    asm volatile(
        "mma.sync.aligned.m16n8k8.row.col.f32.tf32.tf32.f32 "
        "{%0,%1,%2,%3}, {%4,%5,%6,%7}, {%8,%9}, {%0,%1,%2,%3};"
        : "+f"(c[0]), "+f"(c[1]), "+f"(c[2]), "+f"(c[3])
        : "r"(a[0]), "r"(a[1]), "r"(a[2]), "r"(a[3]), "r"(b[0]), "r"(b[1]));
}

__global__ __launch_bounds__(256) void sage_linear_kernel(
    const float* __restrict__ A0, const float* __restrict__ A1,
    const float* __restrict__ W0, const float* __restrict__ W1,
    const float* __restrict__ bias, float* __restrict__ out,
    int M, int Ka)
{
    __shared__ float As[128][36];
    __shared__ float Ws[64][36];
    int tid = threadIdx.x;
    int wid = tid >> 5, lane = tid & 31;
    int wm = wid & 3, wn = wid >> 2;
    int g = lane >> 2, tg = lane & 3;
    int bm = blockIdx.x, bn = blockIdx.y;

    float c[2][4][4];
#pragma unroll
    for (int i = 0; i < 2; i++)
#pragma unroll
        for (int j = 0; j < 4; j++)
#pragma unroll
            for (int k = 0; k < 4; k++) c[i][j][k] = 0.f;

#pragma unroll
    for (int part = 0; part < 2; part++) {
        const float* Asrc = part ? A1 : A0;
        const float* Wsrc = part ? W1 : W0;
        for (int kb = 0; kb < Ka; kb += 32) {
#pragma unroll
            for (int i = 0; i < 4; i++) {
                int l = tid + i * 256;
                int row = l >> 3, c4 = l & 7;
                int gr = bm * 128 + row;
                float4 v = make_float4(0.f, 0.f, 0.f, 0.f);
                if (gr < M) v = *reinterpret_cast<const float4*>(Asrc + (size_t)gr * Ka + kb + c4 * 4);
                *reinterpret_cast<float4*>(&As[row][c4 * 4]) = v;
            }
#pragma unroll
            for (int i = 0; i < 2; i++) {
                int l = tid + i * 256;
                int row = l >> 3, c4 = l & 7;
                int gj = bn * 64 + row;
                float4 v = *reinterpret_cast<const float4*>(Wsrc + (size_t)gj * Ka + kb + c4 * 4);
                *reinterpret_cast<float4*>(&Ws[row][c4 * 4]) = v;
            }
            __syncthreads();
#pragma unroll
            for (int kk = 0; kk < 32; kk += 8) {
                unsigned a[2][4], bf[4][2];
#pragma unroll
                for (int mi = 0; mi < 2; mi++) {
                    int rm = wm * 32 + mi * 16;
                    a[mi][0] = f2tf32(As[rm + g][kk + tg]);
                    a[mi][1] = f2tf32(As[rm + g + 8][kk + tg]);
                    a[mi][2] = f2tf32(As[rm + g][kk + tg + 4]);
                    a[mi][3] = f2tf32(As[rm + g + 8][kk + tg + 4]);
                }
#pragma unroll
                for (int ni = 0; ni < 4; ni++) {
                    int jn = wn * 32 + ni * 8 + g;
                    bf[ni][0] = f2tf32(Ws[jn][kk + tg]);
                    bf[ni][1] = f2tf32(Ws[jn][kk + tg + 4]);
                }
#pragma unroll
                for (int mi = 0; mi < 2; mi++)
#pragma unroll
                    for (int ni = 0; ni < 4; ni++)
                        mma_tf32(c[mi][ni], a[mi], bf[ni]);
            }
            __syncthreads();
        }
    }

#pragma unroll
    for (int mi = 0; mi < 2; mi++) {
        int row0 = bm * 128 + wm * 32 + mi * 16 + g;
        int row1 = row0 + 8;
#pragma unroll
        for (int ni = 0; ni < 4; ni++) {
            int col = bn * 64 + wn * 32 + ni * 8 + 2 * tg;
            float b0 = bias[col], b1v = bias[col + 1];
            float v00 = fmaxf(c[mi][ni][0] + b0, 0.f);
            float v01 = fmaxf(c[mi][ni][1] + b1v, 0.f);
            float v10 = fmaxf(c[mi][ni][2] + b0, 0.f);
            float v11 = fmaxf(c[mi][ni][3] + b1v, 0.f);
            if (row0 < M) { out[(size_t)row0 * HID + col] = v00; out[(size_t)row0 * HID + col + 1] = v01; }
            if (row1 < M) { out[(size_t)row1 * HID + col] = v10; out[(size_t)row1 * HID + col + 1] = v11; }
        }
    }
}

// ---------------- gate: gate[n] = h[n,:] . Wg + bg  (warp per node, float4) ----------------
__global__ void gate_kernel(const float* __restrict__ h, const float* __restrict__ Wg,
                            const float* __restrict__ bg, float* __restrict__ gate) {
    int gw = (blockIdx.x * blockDim.x + threadIdx.x) >> 5;
    int lane = threadIdx.x & 31;
    int nw = (gridDim.x * blockDim.x) >> 5;
    const float4* h4 = reinterpret_cast<const float4*>(h);
    const float4* w4 = reinterpret_cast<const float4*>(Wg);
    float4 wa = w4[lane], wb = w4[32 + lane];
    for (int n = gw; n < N_NODES; n += nw) {
        float4 ha = h4[(size_t)n * 64 + lane];
        float4 hb = h4[(size_t)n * 64 + 32 + lane];
        float s = ha.x * wa.x + ha.y * wa.y + ha.z * wa.z + ha.w * wa.w
                + hb.x * wb.x + hb.y * wb.y + hb.z * wb.z + hb.w * wb.w;
#pragma unroll
        for (int o = 16; o > 0; o >>= 1) s += __shfl_xor_sync(0xffffffff, s, o);
        if (lane == 0) gate[n] = s + bg[0];
    }
}

// ---------------- batch segment bounds ----------------
__global__ void batch_bounds_kernel(const int* __restrict__ batch) {
    int b = threadIdx.x;
    if (b > NB) return;
    if (b == NB) { d_bstart[NB] = N_NODES; return; }
    int lo = 0, hi = N_NODES;
    while (lo < hi) {
        int mid = (lo + hi) >> 1;
        if (batch[mid] < b) lo = mid + 1; else hi = mid;
    }
    d_bstart[b] = lo;
}

// ---------------- pool stats: per-batch max + sumexp, zero pooled ----------------
__global__ void pool_stats_kernel(const float* __restrict__ gate) {
    int b = blockIdx.x, tid = threadIdx.x;
    int beg = d_bstart[b], end = d_bstart[b + 1];
    __shared__ float red[256];

    float m = -3.4e38f;
    for (int n = beg + tid; n < end; n += 256) m = fmaxf(m, gate[n]);
    red[tid] = m; __syncthreads();
    for (int o = 128; o > 0; o >>= 1) { if (tid < o) red[tid] = fmaxf(red[tid], red[tid + o]); __syncthreads(); }
    float mx = red[0]; __syncthreads();

    float s = 0.f;
    for (int n = beg + tid; n < end; n += 256) s += expf(gate[n] - mx);
    red[tid] = s; __syncthreads();
    for (int o = 128; o > 0; o >>= 1) { if (tid < o) red[tid] += red[tid + o]; __syncthreads(); }

    if (tid == 0) { d_pmax[b] = mx; d_psum[b] = fmaxf(red[0], 1e-38f); }
    d_pooled[b * HID + tid] = 0.f;
}

// ---------------- pool accumulate: grid (NB, SPLIT), float4 + atomicAdd ----------------
#define PSPLIT 8
__global__ __launch_bounds__(64) void pool_acc_kernel(const float* __restrict__ h,
                                                      const float* __restrict__ gate) {
    int b = blockIdx.x, sp = blockIdx.y, t = threadIdx.x;
    int beg = d_bstart[b], end = d_bstart[b + 1];
    float mx = d_pmax[b];
    float inv = 1.0f / d_psum[b];
    const float4* h4 = reinterpret_cast<const float4*>(h);
    float4 acc = make_float4(0.f, 0.f, 0.f, 0.f);
    for (int n = beg + sp; n < end; n += PSPLIT) {
        float w = __expf(gate[n] - mx) * inv;
        float4 v = h4[(size_t)n * 64 + t];
        acc.x += w * v.x; acc.y += w * v.y; acc.z += w * v.z; acc.w += w * v.w;
    }
    float* p = &d_pooled[b * HID + t * 4];
    atomicAdd(p + 0, acc.x);
    atomicAdd(p + 1, acc.y);
    atomicAdd(p + 2, acc.z);
    atomicAdd(p + 3, acc.w);
}

// ---------------- MLP head + log_softmax ----------------
__global__ void head_kernel(const float* __restrict__ W1, const float* __restrict__ b1,
                            const float* __restrict__ W2, const float* __restrict__ b2,
                            float* __restrict__ out) {
    int b = blockIdx.x, t = threadIdx.x;
    __shared__ float pin[HID], m1[HID];
    __shared__ float logits[NC];
    pin[t] = d_pooled[b * HID + t];
    __syncthreads();
    float acc = b1[t];
#pragma unroll 8
    for (int k = 0; k < HID; k++) acc += pin[k] * W1[t * HID + k];
    m1[t] = fmaxf(acc, 0.f);
    __syncthreads();
    if (t < NC) {
        float a = b2[t];
        for (int k = 0; k < HID; k++) a += m1[k] * W2[t * HID + k];
        logits[t] = a;
    }
    __syncthreads();
    if (t == 0) {
        float mx = logits[0];
        for (int c2 = 1; c2 < NC; c2++) mx = fmaxf(mx, logits[c2]);
        float s = 0.f;
        for (int c2 = 0; c2 < NC; c2++) s += expf(logits[c2] - mx);
        float lse = mx + logf(s);
        for (int c2 = 0; c2 < NC; c2++) out[b * NC + c2] = logits[c2] - lse;
    }
}

// ---------------- launch ----------------
extern "C" void kernel_launch(void* const* d_in, const int* in_sizes, int n_in,
                              void* d_out, int out_size) {
    const float* x      = (const float*)d_in[0];
    const int* ei       = (const int*)d_in[1];
    const int* batch    = (const int*)d_in[2];
    const float* W1l = (const float*)d_in[3];
    const float* b1l = (const float*)d_in[4];
    const float* W1r = (const float*)d_in[5];
    const float* W2l = (const float*)d_in[6];
    const float* b2l = (const float*)d_in[7];
    const float* W2r = (const float*)d_in[8];
    const float* W3l = (const float*)d_in[9];
    const float* b3l = (const float*)d_in[10];
    const float* W3r = (const float*)d_in[11];
    const float* Wg  = (const float*)d_in[12];
    const float* bg  = (const float*)d_in[13];
    const float* Wl1 = (const float*)d_in[14];
    const float* bl1 = (const float*)d_in[15];
    const float* Wl2 = (const float*)d_in[16];
    const float* bl2 = (const float*)d_in[17];
    float* out = (float*)d_out;

    void *p_agg_, *p_h1_, *p_h2_, *p_gate_;
    cudaGetSymbolAddress(&p_agg_, d_agg);
    cudaGetSymbolAddress(&p_h1_, d_h1);
    cudaGetSymbolAddress(&p_h2_, d_h2);
    cudaGetSymbolAddress(&p_gate_, d_gate);
    float* p_agg = (float*)p_agg_;
    float* p_h1 = (float*)p_h1_;
    float* p_h2 = (float*)p_h2_;
    float* p_gate = (float*)p_gate_;

    const int eblocks = (E_EDGES + 255) / 256;

    // CSR build
    zero_deg_kernel<<<(N_NODES + 255) / 256, 256>>>();
    hist_kernel<<<eblocks, 256>>>(ei);
    scan_kernel<<<1, 1024>>>(N_NODES);
    fill_kernel<<<eblocks, 256>>>(ei);

    dim3 gemm_grid((N_NODES + 127) / 128, HID / 64);

    // layer 1 (Ka = 128)
    aggregate_kernel_v<F_IN / 4><<<N_NODES, F_IN / 4>>>(x, p_agg);
    sage_linear_kernel<<<gemm_grid, 256>>>(p_agg, x, W1l, W1r, b1l, p_h1, N_NODES, F_IN);
    // layer 2
    aggregate_kernel_v<HID / 4><<<N_NODES, HID / 4>>>(p_h1, p_agg);
    sage_linear_kernel<<<gemm_grid, 256>>>(p_agg, p_h1, W2l, W2r, b2l, p_h2, N_NODES, HID);
    // layer 3
    aggregate_kernel_v<HID / 4><<<N_NODES, HID / 4>>>(p_h2, p_agg);
    sage_linear_kernel<<<gemm_grid, 256>>>(p_agg, p_h2, W3l, W3r, b3l, p_h1, N_NODES, HID);

    // pooling + head
    gate_kernel<<<256, 256>>>(p_h1, Wg, bg, p_gate);
    batch_bounds_kernel<<<1, NB + 1>>>(batch);
    pool_stats_kernel<<<NB, 256>>>(p_gate);
    pool_acc_kernel<<<dim3(NB, PSPLIT), 64>>>(p_h1, p_gate);
    head_kernel<<<NB, HID>>>(Wl1, bl1, Wl2, bl2, out);
}

// round 5
// speedup vs baseline: 1.4664x; 1.1349x over previous
#include <cuda_runtime.h>
#include <cuda_bf16.h>
#include <math.h>

#define N_NODES 50000
#define E_EDGES 1600000
#define HID 256
#define F_IN 128
#define NB 64
#define NC 10
#define NSB ((N_NODES + 255) / 256)

// ---------------- static device scratch ----------------
__device__ float d_agg[(size_t)N_NODES * HID];
__device__ float d_h1[(size_t)N_NODES * HID];
__device__ float d_h2[(size_t)N_NODES * HID];
__device__ __nv_bfloat16 d_hb[(size_t)N_NODES * HID];   // bf16 copy of current h for gather
__device__ __nv_bfloat16 d_xb[(size_t)N_NODES * F_IN];  // bf16 copy of x
__device__ int   d_deg[N_NODES];
__device__ float d_invdeg[N_NODES];
__device__ int   d_rowptr[N_NODES + 1];
__device__ int   d_cursor[N_NODES];
__device__ int   d_srcs[E_EDGES];
__device__ int   d_bsum[NSB];
__device__ float d_gate[N_NODES];
__device__ int   d_bstart[NB + 1];
__device__ float d_pooled[NB * HID];
__device__ float d_pmax[NB];
__device__ float d_psum[NB];

__device__ __forceinline__ float2 bf2f(unsigned u) {
    __nv_bfloat162 b = *reinterpret_cast<__nv_bfloat162*>(&u);
    return __bfloat1622float2(b);
}

// ---------------- zero degree array ----------------
__global__ void zero_deg_kernel() {
    int i = blockIdx.x * blockDim.x + threadIdx.x;
    if (i < N_NODES) d_deg[i] = 0;
}

// ---------------- CSR build (edge_index int32) ----------------
__global__ void hist_kernel(const int* __restrict__ ei) {
    int e = blockIdx.x * blockDim.x + threadIdx.x;
    if (e >= E_EDGES) return;
    int dst = ei[E_EDGES + e];
    if ((unsigned)dst < (unsigned)N_NODES) atomicAdd(&d_deg[dst], 1);
}

// 3-phase scan: block reduce -> scan partials -> local scan + offset
__global__ void scan_phaseA() {
    __shared__ int sd[256];
    int tid = threadIdx.x;
    int i = blockIdx.x * 256 + tid;
    sd[tid] = (i < N_NODES) ? d_deg[i] : 0;
    __syncthreads();
    for (int o = 128; o > 0; o >>= 1) { if (tid < o) sd[tid] += sd[tid + o]; __syncthreads(); }
    if (tid == 0) d_bsum[blockIdx.x] = sd[0];
}

__global__ void scan_phaseB() {
    __shared__ int sd[256];
    int tid = threadIdx.x;
    int v = (tid < NSB) ? d_bsum[tid] : 0;
    sd[tid] = v;
    __syncthreads();
    for (int off = 1; off < 256; off <<= 1) {
        int t = (tid >= off) ? sd[tid - off] : 0;
        __syncthreads();
        sd[tid] += t;
        __syncthreads();
    }
    if (tid < NSB) d_bsum[tid] = sd[tid] - v;    // exclusive
    if (tid == 0) d_rowptr[N_NODES] = sd[255];   // total
}

__global__ void scan_phaseC() {
    __shared__ int sd[256];
    int tid = threadIdx.x;
    int i = blockIdx.x * 256 + tid;
    int v = (i < N_NODES) ? d_deg[i] : 0;
    sd[tid] = v;
    __syncthreads();
    for (int off = 1; off < 256; off <<= 1) {
        int t = (tid >= off) ? sd[tid - off] : 0;
        __syncthreads();
        sd[tid] += t;
        __syncthreads();
    }
    if (i < N_NODES) {
        int excl = d_bsum[blockIdx.x] + sd[tid] - v;
        d_rowptr[i] = excl;
        d_cursor[i] = excl;
        d_invdeg[i] = 1.0f / (float)max(v, 1);
    }
}

__global__ void fill_kernel(const int* __restrict__ ei) {
    int e = blockIdx.x * blockDim.x + threadIdx.x;
    if (e >= E_EDGES) return;
    int src = ei[e];
    int dst = ei[E_EDGES + e];
    if ((unsigned)dst >= (unsigned)N_NODES || (unsigned)src >= (unsigned)N_NODES) return;
    int pos = atomicAdd(&d_cursor[dst], 1);
    d_srcs[pos] = src;
}

// ---------------- x -> bf16 convert ----------------
__global__ void convert_x_kernel(const float* __restrict__ x) {
    int i = blockIdx.x * blockDim.x + threadIdx.x;
    if (i >= N_NODES * F_IN / 4) return;
    float4 v = reinterpret_cast<const float4*>(x)[i];
    __nv_bfloat162 lo = __floats2bfloat162_rn(v.x, v.y);
    __nv_bfloat162 hi = __floats2bfloat162_rn(v.z, v.w);
    uint2 o;
    o.x = *reinterpret_cast<unsigned*>(&lo);
    o.y = *reinterpret_cast<unsigned*>(&hi);
    reinterpret_cast<uint2*>(d_xb)[i] = o;
}

// ---------------- bf16 gather aggregation, K=256 ----------------
// one block of 64 threads per node; thread handles 4 features (uint2 = 4 bf16)
__global__ __launch_bounds__(64) void aggregate_bf16_k256(const __nv_bfloat16* __restrict__ xin,
                                                          float* __restrict__ agg) {
    int n = blockIdx.x, t = threadIdx.x;
    int beg = d_rowptr[n], end = d_rowptr[n + 1];
    const uint2* __restrict__ x2 = reinterpret_cast<const uint2*>(xin);
    __shared__ int sidx[64];
    float ax = 0.f, ay = 0.f, az = 0.f, aw = 0.f;
    for (int base = beg; base < end; base += 64) {
        int cnt = min(64, end - base);
        if (t < cnt) sidx[t] = d_srcs[base + t];
        __syncthreads();
        int i = 0;
        for (; i + 4 <= cnt; i += 4) {
            uint2 v0 = x2[(size_t)sidx[i]     * 64 + t];
            uint2 v1 = x2[(size_t)sidx[i + 1] * 64 + t];
            uint2 v2 = x2[(size_t)sidx[i + 2] * 64 + t];
            uint2 v3 = x2[(size_t)sidx[i + 3] * 64 + t];
            float2 f;
            f = bf2f(v0.x); ax += f.x; ay += f.y;  f = bf2f(v0.y); az += f.x; aw += f.y;
            f = bf2f(v1.x); ax += f.x; ay += f.y;  f = bf2f(v1.y); az += f.x; aw += f.y;
            f = bf2f(v2.x); ax += f.x; ay += f.y;  f = bf2f(v2.y); az += f.x; aw += f.y;
            f = bf2f(v3.x); ax += f.x; ay += f.y;  f = bf2f(v3.y); az += f.x; aw += f.y;
        }
        for (; i < cnt; i++) {
            uint2 v = x2[(size_t)sidx[i] * 64 + t];
            float2 f;
            f = bf2f(v.x); ax += f.x; ay += f.y;  f = bf2f(v.y); az += f.x; aw += f.y;
        }
        __syncthreads();
    }
    float inv = d_invdeg[n];
    reinterpret_cast<float4*>(agg)[(size_t)n * 64 + t] =
        make_float4(ax * inv, ay * inv, az * inv, aw * inv);
}

// ---------------- bf16 gather aggregation, K=128 ----------------
// one block of 64 threads per node; thread handles 2 features (unsigned = 2 bf16)
__global__ __launch_bounds__(64) void aggregate_bf16_k128(const __nv_bfloat16* __restrict__ xin,
                                                          float* __restrict__ agg) {
    int n = blockIdx.x, t = threadIdx.x;
    int beg = d_rowptr[n], end = d_rowptr[n + 1];
    const unsigned* __restrict__ x1 = reinterpret_cast<const unsigned*>(xin);
    __shared__ int sidx[64];
    float ax = 0.f, ay = 0.f;
    for (int base = beg; base < end; base += 64) {
        int cnt = min(64, end - base);
        if (t < cnt) sidx[t] = d_srcs[base + t];
        __syncthreads();
        int i = 0;
        for (; i + 4 <= cnt; i += 4) {
            unsigned v0 = x1[(size_t)sidx[i]     * 64 + t];
            unsigned v1 = x1[(size_t)sidx[i + 1] * 64 + t];
            unsigned v2 = x1[(size_t)sidx[i + 2] * 64 + t];
            unsigned v3 = x1[(size_t)sidx[i + 3] * 64 + t];
            float2 f;
            f = bf2f(v0); ax += f.x; ay += f.y;
            f = bf2f(v1); ax += f.x; ay += f.y;
            f = bf2f(v2); ax += f.x; ay += f.y;
            f = bf2f(v3); ax += f.x; ay += f.y;
        }
        for (; i < cnt; i++) {
            float2 f = bf2f(x1[(size_t)sidx[i] * 64 + t]);
            ax += f.x; ay += f.y;
        }
        __syncthreads();
    }
    float inv = d_invdeg[n];
    reinterpret_cast<float2*>(agg)[(size_t)n * 64 + t] = make_float2(ax * inv, ay * inv);
}

// ---------------- TF32 tensor-core fused SAGE linear ----------------
__device__ __forceinline__ unsigned f2tf32(float f) {
    unsigned u;
    asm("cvt.rna.tf32.f32 %0, %1;" : "=r"(u) : "f"(f));
    return u;
}

__device__ __forceinline__ void mma_tf32(float c[4], const unsigned a[4], const unsigned b[2]) {
    asm volatile(
        "mma.sync.aligned.m16n8k8.row.col.f32.tf32.tf32.f32 "
        "{%0,%1,%2,%3}, {%4,%5,%6,%7}, {%8,%9}, {%0,%1,%2,%3};"
        : "+f"(c[0]), "+f"(c[1]), "+f"(c[2]), "+f"(c[3])
        : "r"(a[0]), "r"(a[1]), "r"(a[2]), "r"(a[3]), "r"(b[0]), "r"(b[1]));
}

__global__ __launch_bounds__(256) void sage_linear_kernel(
    const float* __restrict__ A0, const float* __restrict__ A1,
    const float* __restrict__ W0, const float* __restrict__ W1,
    const float* __restrict__ bias, float* __restrict__ out,
    __nv_bfloat16* __restrict__ outb,   // optional bf16 copy for next gather
    int M, int Ka)
{
    __shared__ float As[128][36];
    __shared__ float Ws[64][36];
    int tid = threadIdx.x;
    int wid = tid >> 5, lane = tid & 31;
    int wm = wid & 3, wn = wid >> 2;
    int g = lane >> 2, tg = lane & 3;
    int bm = blockIdx.x, bn = blockIdx.y;

    float c[2][4][4];
#pragma unroll
    for (int i = 0; i < 2; i++)
#pragma unroll
        for (int j = 0; j < 4; j++)
#pragma unroll
            for (int k = 0; k < 4; k++) c[i][j][k] = 0.f;

#pragma unroll
    for (int part = 0; part < 2; part++) {
        const float* Asrc = part ? A1 : A0;
        const float* Wsrc = part ? W1 : W0;
        for (int kb = 0; kb < Ka; kb += 32) {
#pragma unroll
            for (int i = 0; i < 4; i++) {
                int l = tid + i * 256;
                int row = l >> 3, c4 = l & 7;
                int gr = bm * 128 + row;
                float4 v = make_float4(0.f, 0.f, 0.f, 0.f);
                if (gr < M) v = *reinterpret_cast<const float4*>(Asrc + (size_t)gr * Ka + kb + c4 * 4);
                *reinterpret_cast<float4*>(&As[row][c4 * 4]) = v;
            }
#pragma unroll
            for (int i = 0; i < 2; i++) {
                int l = tid + i * 256;
                int row = l >> 3, c4 = l & 7;
                int gj = bn * 64 + row;
                float4 v = *reinterpret_cast<const float4*>(Wsrc + (size_t)gj * Ka + kb + c4 * 4);
                *reinterpret_cast<float4*>(&Ws[row][c4 * 4]) = v;
            }
            __syncthreads();
#pragma unroll
            for (int kk = 0; kk < 32; kk += 8) {
                unsigned a[2][4], bf[4][2];
#pragma unroll
                for (int mi = 0; mi < 2; mi++) {
                    int rm = wm * 32 + mi * 16;
                    a[mi][0] = f2tf32(As[rm + g][kk + tg]);
                    a[mi][1] = f2tf32(As[rm + g + 8][kk + tg]);
                    a[mi][2] = f2tf32(As[rm + g][kk + tg + 4]);
                    a[mi][3] = f2tf32(As[rm + g + 8][kk + tg + 4]);
                }
#pragma unroll
                for (int ni = 0; ni < 4; ni++) {
                    int jn = wn * 32 + ni * 8 + g;
                    bf[ni][0] = f2tf32(Ws[jn][kk + tg]);
                    bf[ni][1] = f2tf32(Ws[jn][kk + tg + 4]);
                }
#pragma unroll
                for (int mi = 0; mi < 2; mi++)
#pragma unroll
                    for (int ni = 0; ni < 4; ni++)
                        mma_tf32(c[mi][ni], a[mi], bf[ni]);
            }
            __syncthreads();
        }
    }

#pragma unroll
    for (int mi = 0; mi < 2; mi++) {
        int row0 = bm * 128 + wm * 32 + mi * 16 + g;
        int row1 = row0 + 8;
#pragma unroll
        for (int ni = 0; ni < 4; ni++) {
            int col = bn * 64 + wn * 32 + ni * 8 + 2 * tg;
            float b0 = bias[col], b1v = bias[col + 1];
            float v00 = fmaxf(c[mi][ni][0] + b0, 0.f);
            float v01 = fmaxf(c[mi][ni][1] + b1v, 0.f);
            float v10 = fmaxf(c[mi][ni][2] + b0, 0.f);
            float v11 = fmaxf(c[mi][ni][3] + b1v, 0.f);
            if (row0 < M) {
                out[(size_t)row0 * HID + col] = v00;
                out[(size_t)row0 * HID + col + 1] = v01;
                if (outb) {
                    __nv_bfloat162 p = __floats2bfloat162_rn(v00, v01);
                    reinterpret_cast<__nv_bfloat162*>(outb)[((size_t)row0 * HID + col) >> 1] = p;
                }
            }
            if (row1 < M) {
                out[(size_t)row1 * HID + col] = v10;
                out[(size_t)row1 * HID + col + 1] = v11;
                if (outb) {
                    __nv_bfloat162 p = __floats2bfloat162_rn(v10, v11);
                    reinterpret_cast<__nv_bfloat162*>(outb)[((size_t)row1 * HID + col) >> 1] = p;
                }
            }
        }
    }
}

// ---------------- gate: warp per node, float4 ----------------
__global__ void gate_kernel(const float* __restrict__ h, const float* __restrict__ Wg,
                            const float* __restrict__ bg, float* __restrict__ gate) {
    int gw = (blockIdx.x * blockDim.x + threadIdx.x) >> 5;
    int lane = threadIdx.x & 31;
    int nw = (gridDim.x * blockDim.x) >> 5;
    const float4* h4 = reinterpret_cast<const float4*>(h);
    const float4* w4 = reinterpret_cast<const float4*>(Wg);
    float4 wa = w4[lane], wb = w4[32 + lane];
    for (int n = gw; n < N_NODES; n += nw) {
        float4 ha = h4[(size_t)n * 64 + lane];
        float4 hb = h4[(size_t)n * 64 + 32 + lane];
        float s = ha.x * wa.x + ha.y * wa.y + ha.z * wa.z + ha.w * wa.w
                + hb.x * wb.x + hb.y * wb.y + hb.z * wb.z + hb.w * wb.w;
#pragma unroll
        for (int o = 16; o > 0; o >>= 1) s += __shfl_xor_sync(0xffffffff, s, o);
        if (lane == 0) gate[n] = s + bg[0];
    }
}

// ---------------- batch segment bounds ----------------
__global__ void batch_bounds_kernel(const int* __restrict__ batch) {
    int b = threadIdx.x;
    if (b > NB) return;
    if (b == NB) { d_bstart[NB] = N_NODES; return; }
    int lo = 0, hi = N_NODES;
    while (lo < hi) {
        int mid = (lo + hi) >> 1;
        if (batch[mid] < b) lo = mid + 1; else hi = mid;
    }
    d_bstart[b] = lo;
}

// ---------------- pool stats ----------------
__global__ void pool_stats_kernel(const float* __restrict__ gate) {
    int b = blockIdx.x, tid = threadIdx.x;
    int beg = d_bstart[b], end = d_bstart[b + 1];
    __shared__ float red[256];

    float m = -3.4e38f;
    for (int n = beg + tid; n < end; n += 256) m = fmaxf(m, gate[n]);
    red[tid] = m; __syncthreads();
    for (int o = 128; o > 0; o >>= 1) { if (tid < o) red[tid] = fmaxf(red[tid], red[tid + o]); __syncthreads(); }
    float mx = red[0]; __syncthreads();

    float s = 0.f;
    for (int n = beg + tid; n < end; n += 256) s += expf(gate[n] - mx);
    red[tid] = s; __syncthreads();
    for (int o = 128; o > 0; o >>= 1) { if (tid < o) red[tid] += red[tid + o]; __syncthreads(); }

    if (tid == 0) { d_pmax[b] = mx; d_psum[b] = fmaxf(red[0], 1e-38f); }
    d_pooled[b * HID + tid] = 0.f;
}

// ---------------- pool accumulate ----------------
#define PSPLIT 8
__global__ __launch_bounds__(64) void pool_acc_kernel(const float* __restrict__ h,
                                                      const float* __restrict__ gate) {
    int b = blockIdx.x, sp = blockIdx.y, t = threadIdx.x;
    int beg = d_bstart[b], end = d_bstart[b + 1];
    float mx = d_pmax[b];
    float inv = 1.0f / d_psum[b];
    const float4* h4 = reinterpret_cast<const float4*>(h);
    float4 acc = make_float4(0.f, 0.f, 0.f, 0.f);
    for (int n = beg + sp; n < end; n += PSPLIT) {
        float w = __expf(gate[n] - mx) * inv;
        float4 v = h4[(size_t)n * 64 + t];
        acc.x += w * v.x; acc.y += w * v.y; acc.z += w * v.z; acc.w += w * v.w;
    }
    float* p = &d_pooled[b * HID + t * 4];
    atomicAdd(p + 0, acc.x);
    atomicAdd(p + 1, acc.y);
    atomicAdd(p + 2, acc.z);
    atomicAdd(p + 3, acc.w);
}

// ---------------- MLP head + log_softmax ----------------
__global__ void head_kernel(const float* __restrict__ W1, const float* __restrict__ b1,
                            const float* __restrict__ W2, const float* __restrict__ b2,
                            float* __restrict__ out) {
    int b = blockIdx.x, t = threadIdx.x;
    __shared__ float pin[HID], m1[HID];
    __shared__ float logits[NC];
    pin[t] = d_pooled[b * HID + t];
    __syncthreads();
    float acc = b1[t];
#pragma unroll 8
    for (int k = 0; k < HID; k++) acc += pin[k] * W1[t * HID + k];
    m1[t] = fmaxf(acc, 0.f);
    __syncthreads();
    if (t < NC) {
        float a = b2[t];
        for (int k = 0; k < HID; k++) a += m1[k] * W2[t * HID + k];
        logits[t] = a;
    }
    __syncthreads();
    if (t == 0) {
        float mx = logits[0];
        for (int c2 = 1; c2 < NC; c2++) mx = fmaxf(mx, logits[c2]);
        float s = 0.f;
        for (int c2 = 0; c2 < NC; c2++) s += expf(logits[c2] - mx);
        float lse = mx + logf(s);
        for (int c2 = 0; c2 < NC; c2++) out[b * NC + c2] = logits[c2] - lse;
    }
}

// ---------------- launch ----------------
extern "C" void kernel_launch(void* const* d_in, const int* in_sizes, int n_in,
                              void* d_out, int out_size) {
    const float* x      = (const float*)d_in[0];
    const int* ei       = (const int*)d_in[1];
    const int* batch    = (const int*)d_in[2];
    const float* W1l = (const float*)d_in[3];
    const float* b1l = (const float*)d_in[4];
    const float* W1r = (const float*)d_in[5];
    const float* W2l = (const float*)d_in[6];
    const float* b2l = (const float*)d_in[7];
    const float* W2r = (const float*)d_in[8];
    const float* W3l = (const float*)d_in[9];
    const float* b3l = (const float*)d_in[10];
    const float* W3r = (const float*)d_in[11];
    const float* Wg  = (const float*)d_in[12];
    const float* bg  = (const float*)d_in[13];
    const float* Wl1 = (const float*)d_in[14];
    const float* bl1 = (const float*)d_in[15];
    const float* Wl2 = (const float*)d_in[16];
    const float* bl2 = (const float*)d_in[17];
    float* out = (float*)d_out;

    void *p_agg_, *p_h1_, *p_h2_, *p_hb_, *p_xb_, *p_gate_;
    cudaGetSymbolAddress(&p_agg_, d_agg);
    cudaGetSymbolAddress(&p_h1_, d_h1);
    cudaGetSymbolAddress(&p_h2_, d_h2);
    cudaGetSymbolAddress(&p_hb_, d_hb);
    cudaGetSymbolAddress(&p_xb_, d_xb);
    cudaGetSymbolAddress(&p_gate_, d_gate);
    float* p_agg = (float*)p_agg_;
    float* p_h1 = (float*)p_h1_;
    float* p_h2 = (float*)p_h2_;
    __nv_bfloat16* p_hb = (__nv_bfloat16*)p_hb_;
    __nv_bfloat16* p_xb = (__nv_bfloat16*)p_xb_;
    float* p_gate = (float*)p_gate_;

    const int eblocks = (E_EDGES + 255) / 256;

    // CSR build
    zero_deg_kernel<<<(N_NODES + 255) / 256, 256>>>();
    hist_kernel<<<eblocks, 256>>>(ei);
    scan_phaseA<<<NSB, 256>>>();
    scan_phaseB<<<1, 256>>>();
    scan_phaseC<<<NSB, 256>>>();
    fill_kernel<<<eblocks, 256>>>(ei);

    // x -> bf16
    convert_x_kernel<<<(N_NODES * F_IN / 4 + 255) / 256, 256>>>(x);

    dim3 gemm_grid((N_NODES + 127) / 128, HID / 64);

    // layer 1 (Ka = 128): gather bf16 x, GEMM f32, write h1 f32 + bf16
    aggregate_bf16_k128<<<N_NODES, 64>>>(p_xb, p_agg);
    sage_linear_kernel<<<gemm_grid, 256>>>(p_agg, x, W1l, W1r, b1l, p_h1, p_hb, N_NODES, F_IN);
    // layer 2
    aggregate_bf16_k256<<<N_NODES, 64>>>(p_hb, p_agg);
    sage_linear_kernel<<<gemm_grid, 256>>>(p_agg, p_h1, W2l, W2r, b2l, p_h2, p_hb, N_NODES, HID);
    // layer 3 (h3 only feeds gate/pool -> no bf16 copy)
    aggregate_bf16_k256<<<N_NODES, 64>>>(p_hb, p_agg);
    sage_linear_kernel<<<gemm_grid, 256>>>(p_agg, p_h2, W3l, W3r, b3l, p_h1, nullptr, N_NODES, HID);

    // pooling + head
    gate_kernel<<<256, 256>>>(p_h1, Wg, bg, p_gate);
    batch_bounds_kernel<<<1, NB + 1>>>(batch);
    pool_stats_kernel<<<NB, 256>>>(p_gate);
    pool_acc_kernel<<<dim3(NB, PSPLIT), 64>>>(p_h1, p_gate);
    head_kernel<<<NB, HID>>>(Wl1, bl1, Wl2, bl2, out);
}

// round 6
// speedup vs baseline: 2.1778x; 1.4852x over previous
#include <cuda_runtime.h>
#include <cuda_bf16.h>
#include <math.h>

#define N_NODES 50000
#define E_EDGES 1600000
#define HID 256
#define F_IN 128
#define NB 64
#define NC 10
#define NSB ((N_NODES + 255) / 256)

// ---------------- static device scratch ----------------
__device__ __nv_bfloat16 d_aggb[(size_t)N_NODES * HID];  // bf16 aggregated neighbors
__device__ __nv_bfloat16 d_hb1[(size_t)N_NODES * HID];   // bf16 h (ping)
__device__ __nv_bfloat16 d_hb2[(size_t)N_NODES * HID];   // bf16 h (pong)
__device__ __nv_bfloat16 d_xb[(size_t)N_NODES * F_IN];   // bf16 x
__device__ __nv_bfloat16 d_wb[327680];                    // bf16 weights (6 mats)
__device__ float d_h3[(size_t)N_NODES * HID];            // fp32 final h (gate/pool)
__device__ int   d_deg[N_NODES];
__device__ float d_invdeg[N_NODES];
__device__ int   d_rowptr[N_NODES + 1];
__device__ int   d_cursor[N_NODES];
__device__ int   d_srcs[E_EDGES];
__device__ int   d_bsum[NSB];
__device__ float d_gate[N_NODES];
__device__ int   d_bstart[NB + 1];
__device__ float d_pooled[NB * HID];
__device__ float d_pmax[NB];
__device__ float d_psum[NB];

// weight offsets in d_wb
#define OFF_W1L 0
#define OFF_W1R 32768
#define OFF_W2L 65536
#define OFF_W2R 131072
#define OFF_W3L 196608
#define OFF_W3R 262144
#define W_TOTAL 327680

__device__ __forceinline__ float2 bf2f(unsigned u) {
    __nv_bfloat162 b = *reinterpret_cast<__nv_bfloat162*>(&u);
    return __bfloat1622float2(b);
}
__device__ __forceinline__ unsigned f2bf2(float a, float b) {
    __nv_bfloat162 p = __floats2bfloat162_rn(a, b);
    return *reinterpret_cast<unsigned*>(&p);
}

// ---------------- zero degree ----------------
__global__ void zero_deg_kernel() {
    int i = blockIdx.x * blockDim.x + threadIdx.x;
    if (i < N_NODES) d_deg[i] = 0;
}

// ---------------- CSR build ----------------
__global__ void hist_kernel(const int* __restrict__ ei) {
    int e = blockIdx.x * blockDim.x + threadIdx.x;
    if (e >= E_EDGES) return;
    int dst = ei[E_EDGES + e];
    if ((unsigned)dst < (unsigned)N_NODES) atomicAdd(&d_deg[dst], 1);
}

__global__ void scan_phaseA() {
    __shared__ int sd[256];
    int tid = threadIdx.x;
    int i = blockIdx.x * 256 + tid;
    sd[tid] = (i < N_NODES) ? d_deg[i] : 0;
    __syncthreads();
    for (int o = 128; o > 0; o >>= 1) { if (tid < o) sd[tid] += sd[tid + o]; __syncthreads(); }
    if (tid == 0) d_bsum[blockIdx.x] = sd[0];
}

__global__ void scan_phaseB() {
    __shared__ int sd[256];
    int tid = threadIdx.x;
    int v = (tid < NSB) ? d_bsum[tid] : 0;
    sd[tid] = v;
    __syncthreads();
    for (int off = 1; off < 256; off <<= 1) {
        int t = (tid >= off) ? sd[tid - off] : 0;
        __syncthreads();
        sd[tid] += t;
        __syncthreads();
    }
    if (tid < NSB) d_bsum[tid] = sd[tid] - v;
    if (tid == 0) d_rowptr[N_NODES] = sd[255];
}

__global__ void scan_phaseC() {
    __shared__ int sd[256];
    int tid = threadIdx.x;
    int i = blockIdx.x * 256 + tid;
    int v = (i < N_NODES) ? d_deg[i] : 0;
    sd[tid] = v;
    __syncthreads();
    for (int off = 1; off < 256; off <<= 1) {
        int t = (tid >= off) ? sd[tid - off] : 0;
        __syncthreads();
        sd[tid] += t;
        __syncthreads();
    }
    if (i < N_NODES) {
        int excl = d_bsum[blockIdx.x] + sd[tid] - v;
        d_rowptr[i] = excl;
        d_cursor[i] = excl;
        d_invdeg[i] = 1.0f / (float)max(v, 1);
    }
}

__global__ void fill_kernel(const int* __restrict__ ei) {
    int e = blockIdx.x * blockDim.x + threadIdx.x;
    if (e >= E_EDGES) return;
    int src = ei[e];
    int dst = ei[E_EDGES + e];
    if ((unsigned)dst >= (unsigned)N_NODES || (unsigned)src >= (unsigned)N_NODES) return;
    int pos = atomicAdd(&d_cursor[dst], 1);
    d_srcs[pos] = src;
}

// ---------------- converts ----------------
__global__ void convert_x_kernel(const float* __restrict__ x) {
    int i = blockIdx.x * blockDim.x + threadIdx.x;
    if (i >= N_NODES * F_IN / 4) return;
    float4 v = reinterpret_cast<const float4*>(x)[i];
    uint2 o;
    o.x = f2bf2(v.x, v.y);
    o.y = f2bf2(v.z, v.w);
    reinterpret_cast<uint2*>(d_xb)[i] = o;
}

__global__ void convert_w_kernel(const float* __restrict__ W1l, const float* __restrict__ W1r,
                                 const float* __restrict__ W2l, const float* __restrict__ W2r,
                                 const float* __restrict__ W3l, const float* __restrict__ W3r) {
    int i = blockIdx.x * blockDim.x + threadIdx.x;
    if (i >= W_TOTAL) return;
    float v;
    if      (i < OFF_W1R) v = W1l[i - OFF_W1L];
    else if (i < OFF_W2L) v = W1r[i - OFF_W1R];
    else if (i < OFF_W2R) v = W2l[i - OFF_W2L];
    else if (i < OFF_W3L) v = W2r[i - OFF_W2R];
    else if (i < OFF_W3R) v = W3l[i - OFF_W3L];
    else                  v = W3r[i - OFF_W3R];
    d_wb[i] = __float2bfloat16_rn(v);
}

// ---------------- bf16 gather aggregation, K=256 (4 feats/thread) ----------------
__global__ __launch_bounds__(64) void aggregate_bf16_k256(const __nv_bfloat16* __restrict__ xin,
                                                          __nv_bfloat16* __restrict__ agg) {
    int n = blockIdx.x, t = threadIdx.x;
    int beg = d_rowptr[n], end = d_rowptr[n + 1];
    const uint2* __restrict__ x2 = reinterpret_cast<const uint2*>(xin);
    __shared__ int sidx[64];
    float ax = 0.f, ay = 0.f, az = 0.f, aw = 0.f;
    for (int base = beg; base < end; base += 64) {
        int cnt = min(64, end - base);
        if (t < cnt) sidx[t] = d_srcs[base + t];
        __syncthreads();
        int i = 0;
        for (; i + 4 <= cnt; i += 4) {
            uint2 v0 = x2[(size_t)sidx[i]     * 64 + t];
            uint2 v1 = x2[(size_t)sidx[i + 1] * 64 + t];
            uint2 v2 = x2[(size_t)sidx[i + 2] * 64 + t];
            uint2 v3 = x2[(size_t)sidx[i + 3] * 64 + t];
            float2 f;
            f = bf2f(v0.x); ax += f.x; ay += f.y;  f = bf2f(v0.y); az += f.x; aw += f.y;
            f = bf2f(v1.x); ax += f.x; ay += f.y;  f = bf2f(v1.y); az += f.x; aw += f.y;
            f = bf2f(v2.x); ax += f.x; ay += f.y;  f = bf2f(v2.y); az += f.x; aw += f.y;
            f = bf2f(v3.x); ax += f.x; ay += f.y;  f = bf2f(v3.y); az += f.x; aw += f.y;
        }
        for (; i < cnt; i++) {
            uint2 v = x2[(size_t)sidx[i] * 64 + t];
            float2 f;
            f = bf2f(v.x); ax += f.x; ay += f.y;  f = bf2f(v.y); az += f.x; aw += f.y;
        }
        __syncthreads();
    }
    float inv = d_invdeg[n];
    uint2 o;
    o.x = f2bf2(ax * inv, ay * inv);
    o.y = f2bf2(az * inv, aw * inv);
    reinterpret_cast<uint2*>(agg)[(size_t)n * 64 + t] = o;
}

// ---------------- bf16 gather aggregation, K=128 (2 feats/thread) ----------------
__global__ __launch_bounds__(64) void aggregate_bf16_k128(const __nv_bfloat16* __restrict__ xin,
                                                          __nv_bfloat16* __restrict__ agg) {
    int n = blockIdx.x, t = threadIdx.x;
    int beg = d_rowptr[n], end = d_rowptr[n + 1];
    const unsigned* __restrict__ x1 = reinterpret_cast<const unsigned*>(xin);
    __shared__ int sidx[64];
    float ax = 0.f, ay = 0.f;
    for (int base = beg; base < end; base += 64) {
        int cnt = min(64, end - base);
        if (t < cnt) sidx[t] = d_srcs[base + t];
        __syncthreads();
        int i = 0;
        for (; i + 4 <= cnt; i += 4) {
            float2 f;
            f = bf2f(x1[(size_t)sidx[i]     * 64 + t]); ax += f.x; ay += f.y;
            f = bf2f(x1[(size_t)sidx[i + 1] * 64 + t]); ax += f.x; ay += f.y;
            f = bf2f(x1[(size_t)sidx[i + 2] * 64 + t]); ax += f.x; ay += f.y;
            f = bf2f(x1[(size_t)sidx[i + 3] * 64 + t]); ax += f.x; ay += f.y;
        }
        for (; i < cnt; i++) {
            float2 f = bf2f(x1[(size_t)sidx[i] * 64 + t]);
            ax += f.x; ay += f.y;
        }
        __syncthreads();
    }
    float inv = d_invdeg[n];
    reinterpret_cast<unsigned*>(agg)[(size_t)n * 64 + t] = f2bf2(ax * inv, ay * inv);
}

// ---------------- bf16 tensor-core fused SAGE linear ----------------
// out[n,j] = relu(bias[j] + sum_k A0[n,k] W0[j,k] + sum_k A1[n,k] W1[j,k])
__device__ __forceinline__ void mma_bf16(float c[4], const unsigned a[4], const unsigned b[2]) {
    asm volatile(
        "mma.sync.aligned.m16n8k16.row.col.f32.bf16.bf16.f32 "
        "{%0,%1,%2,%3}, {%4,%5,%6,%7}, {%8,%9}, {%0,%1,%2,%3};"
        : "+f"(c[0]), "+f"(c[1]), "+f"(c[2]), "+f"(c[3])
        : "r"(a[0]), "r"(a[1]), "r"(a[2]), "r"(a[3]), "r"(b[0]), "r"(b[1]));
}

__global__ __launch_bounds__(256) void sage_linear_bf16(
    const __nv_bfloat16* __restrict__ A0, const __nv_bfloat16* __restrict__ A1,
    const __nv_bfloat16* __restrict__ W0, const __nv_bfloat16* __restrict__ W1,
    const float* __restrict__ bias, float* __restrict__ outf,
    __nv_bfloat16* __restrict__ outb, int M, int Ka)
{
    // packed bf16x2 tiles, 64-bf16 K panel (=32 uints/row), stride 36 -> conflict-free frags
    __shared__ unsigned As2[128][36];
    __shared__ unsigned Ws2[64][36];
    int tid = threadIdx.x;
    int wid = tid >> 5, lane = tid & 31;
    int wm = wid & 3, wn = wid >> 2;
    int g = lane >> 2, tg = lane & 3;
    int bm = blockIdx.x, bn = blockIdx.y;

    float c[2][4][4];
#pragma unroll
    for (int i = 0; i < 2; i++)
#pragma unroll
        for (int j = 0; j < 4; j++)
#pragma unroll
            for (int k = 0; k < 4; k++) c[i][j][k] = 0.f;

#pragma unroll
    for (int part = 0; part < 2; part++) {
        const __nv_bfloat16* Asrc = part ? A1 : A0;
        const __nv_bfloat16* Wsrc = part ? W1 : W0;
        for (int kb = 0; kb < Ka; kb += 64) {
            // A tile: 128 rows x 64 bf16 (8 x uint4 per row)
#pragma unroll
            for (int i = 0; i < 4; i++) {
                int l = tid + i * 256;
                int row = l >> 3, c8 = l & 7;
                int gr = bm * 128 + row;
                uint4 v = make_uint4(0u, 0u, 0u, 0u);
                if (gr < M) v = *reinterpret_cast<const uint4*>(Asrc + (size_t)gr * Ka + kb + c8 * 8);
                *reinterpret_cast<uint4*>(&As2[row][c8 * 4]) = v;
            }
            // W tile: 64 rows x 64 bf16
#pragma unroll
            for (int i = 0; i < 2; i++) {
                int l = tid + i * 256;
                int row = l >> 3, c8 = l & 7;
                int gj = bn * 64 + row;
                uint4 v = *reinterpret_cast<const uint4*>(Wsrc + (size_t)gj * Ka + kb + c8 * 8);
                *reinterpret_cast<uint4*>(&Ws2[row][c8 * 4]) = v;
            }
            __syncthreads();
#pragma unroll
            for (int kk2 = 0; kk2 < 32; kk2 += 8) {   // k16 per step (8 uints)
                unsigned a[2][4], bfr[4][2];
#pragma unroll
                for (int mi = 0; mi < 2; mi++) {
                    int rm = wm * 32 + mi * 16;
                    a[mi][0] = As2[rm + g][kk2 + tg];
                    a[mi][1] = As2[rm + g + 8][kk2 + tg];
                    a[mi][2] = As2[rm + g][kk2 + tg + 4];
                    a[mi][3] = As2[rm + g + 8][kk2 + tg + 4];
                }
#pragma unroll
                for (int ni = 0; ni < 4; ni++) {
                    int jn = wn * 32 + ni * 8 + g;
                    bfr[ni][0] = Ws2[jn][kk2 + tg];
                    bfr[ni][1] = Ws2[jn][kk2 + tg + 4];
                }
#pragma unroll
                for (int mi = 0; mi < 2; mi++)
#pragma unroll
                    for (int ni = 0; ni < 4; ni++)
                        mma_bf16(c[mi][ni], a[mi], bfr[ni]);
            }
            __syncthreads();
        }
    }

    // epilogue: bias + relu + optional fp32 / bf16 stores
#pragma unroll
    for (int mi = 0; mi < 2; mi++) {
        int row0 = bm * 128 + wm * 32 + mi * 16 + g;
        int row1 = row0 + 8;
#pragma unroll
        for (int ni = 0; ni < 4; ni++) {
            int col = bn * 64 + wn * 32 + ni * 8 + 2 * tg;
            float b0 = bias[col], b1v = bias[col + 1];
            float v00 = fmaxf(c[mi][ni][0] + b0, 0.f);
            float v01 = fmaxf(c[mi][ni][1] + b1v, 0.f);
            float v10 = fmaxf(c[mi][ni][2] + b0, 0.f);
            float v11 = fmaxf(c[mi][ni][3] + b1v, 0.f);
            if (row0 < M) {
                if (outf) {
                    outf[(size_t)row0 * HID + col] = v00;
                    outf[(size_t)row0 * HID + col + 1] = v01;
                }
                if (outb)
                    reinterpret_cast<unsigned*>(outb)[((size_t)row0 * HID + col) >> 1] = f2bf2(v00, v01);
            }
            if (row1 < M) {
                if (outf) {
                    outf[(size_t)row1 * HID + col] = v10;
                    outf[(size_t)row1 * HID + col + 1] = v11;
                }
                if (outb)
                    reinterpret_cast<unsigned*>(outb)[((size_t)row1 * HID + col) >> 1] = f2bf2(v10, v11);
            }
        }
    }
}

// ---------------- gate: warp per node, float4 ----------------
__global__ void gate_kernel(const float* __restrict__ h, const float* __restrict__ Wg,
                            const float* __restrict__ bg, float* __restrict__ gate) {
    int gw = (blockIdx.x * blockDim.x + threadIdx.x) >> 5;
    int lane = threadIdx.x & 31;
    int nw = (gridDim.x * blockDim.x) >> 5;
    const float4* h4 = reinterpret_cast<const float4*>(h);
    const float4* w4 = reinterpret_cast<const float4*>(Wg);
    float4 wa = w4[lane], wb = w4[32 + lane];
    for (int n = gw; n < N_NODES; n += nw) {
        float4 ha = h4[(size_t)n * 64 + lane];
        float4 hb = h4[(size_t)n * 64 + 32 + lane];
        float s = ha.x * wa.x + ha.y * wa.y + ha.z * wa.z + ha.w * wa.w
                + hb.x * wb.x + hb.y * wb.y + hb.z * wb.z + hb.w * wb.w;
#pragma unroll
        for (int o = 16; o > 0; o >>= 1) s += __shfl_xor_sync(0xffffffff, s, o);
        if (lane == 0) gate[n] = s + bg[0];
    }
}

// ---------------- batch segment bounds ----------------
__global__ void batch_bounds_kernel(const int* __restrict__ batch) {
    int b = threadIdx.x;
    if (b > NB) return;
    if (b == NB) { d_bstart[NB] = N_NODES; return; }
    int lo = 0, hi = N_NODES;
    while (lo < hi) {
        int mid = (lo + hi) >> 1;
        if (batch[mid] < b) lo = mid + 1; else hi = mid;
    }
    d_bstart[b] = lo;
}

// ---------------- pool stats ----------------
__global__ void pool_stats_kernel(const float* __restrict__ gate) {
    int b = blockIdx.x, tid = threadIdx.x;
    int beg = d_bstart[b], end = d_bstart[b + 1];
    __shared__ float red[256];

    float m = -3.4e38f;
    for (int n = beg + tid; n < end; n += 256) m = fmaxf(m, gate[n]);
    red[tid] = m; __syncthreads();
    for (int o = 128; o > 0; o >>= 1) { if (tid < o) red[tid] = fmaxf(red[tid], red[tid + o]); __syncthreads(); }
    float mx = red[0]; __syncthreads();

    float s = 0.f;
    for (int n = beg + tid; n < end; n += 256) s += expf(gate[n] - mx);
    red[tid] = s; __syncthreads();
    for (int o = 128; o > 0; o >>= 1) { if (tid < o) red[tid] += red[tid + o]; __syncthreads(); }

    if (tid == 0) { d_pmax[b] = mx; d_psum[b] = fmaxf(red[0], 1e-38f); }
    d_pooled[b * HID + tid] = 0.f;
}

// ---------------- pool accumulate ----------------
#define PSPLIT 8
__global__ __launch_bounds__(64) void pool_acc_kernel(const float* __restrict__ h,
                                                      const float* __restrict__ gate) {
    int b = blockIdx.x, sp = blockIdx.y, t = threadIdx.x;
    int beg = d_bstart[b], end = d_bstart[b + 1];
    float mx = d_pmax[b];
    float inv = 1.0f / d_psum[b];
    const float4* h4 = reinterpret_cast<const float4*>(h);
    float4 acc = make_float4(0.f, 0.f, 0.f, 0.f);
    for (int n = beg + sp; n < end; n += PSPLIT) {
        float w = __expf(gate[n] - mx) * inv;
        float4 v = h4[(size_t)n * 64 + t];
        acc.x += w * v.x; acc.y += w * v.y; acc.z += w * v.z; acc.w += w * v.w;
    }
    float* p = &d_pooled[b * HID + t * 4];
    atomicAdd(p + 0, acc.x);
    atomicAdd(p + 1, acc.y);
    atomicAdd(p + 2, acc.z);
    atomicAdd(p + 3, acc.w);
}

// ---------------- MLP head + log_softmax ----------------
__global__ void head_kernel(const float* __restrict__ W1, const float* __restrict__ b1,
                            const float* __restrict__ W2, const float* __restrict__ b2,
                            float* __restrict__ out) {
    int b = blockIdx.x, t = threadIdx.x;
    __shared__ float pin[HID], m1[HID];
    __shared__ float logits[NC];
    pin[t] = d_pooled[b * HID + t];
    __syncthreads();
    float acc = b1[t];
#pragma unroll 8
    for (int k = 0; k < HID; k++) acc += pin[k] * W1[t * HID + k];
    m1[t] = fmaxf(acc, 0.f);
    __syncthreads();
    if (t < NC) {
        float a = b2[t];
        for (int k = 0; k < HID; k++) a += m1[k] * W2[t * HID + k];
        logits[t] = a;
    }
    __syncthreads();
    if (t == 0) {
        float mx = logits[0];
        for (int c2 = 1; c2 < NC; c2++) mx = fmaxf(mx, logits[c2]);
        float s = 0.f;
        for (int c2 = 0; c2 < NC; c2++) s += expf(logits[c2] - mx);
        float lse = mx + logf(s);
        for (int c2 = 0; c2 < NC; c2++) out[b * NC + c2] = logits[c2] - lse;
    }
}

// ---------------- launch ----------------
extern "C" void kernel_launch(void* const* d_in, const int* in_sizes, int n_in,
                              void* d_out, int out_size) {
    const float* x      = (const float*)d_in[0];
    const int* ei       = (const int*)d_in[1];
    const int* batch    = (const int*)d_in[2];
    const float* W1l = (const float*)d_in[3];
    const float* b1l = (const float*)d_in[4];
    const float* W1r = (const float*)d_in[5];
    const float* W2l = (const float*)d_in[6];
    const float* b2l = (const float*)d_in[7];
    const float* W2r = (const float*)d_in[8];
    const float* W3l = (const float*)d_in[9];
    const float* b3l = (const float*)d_in[10];
    const float* W3r = (const float*)d_in[11];
    const float* Wg  = (const float*)d_in[12];
    const float* bg  = (const float*)d_in[13];
    const float* Wl1 = (const float*)d_in[14];
    const float* bl1 = (const float*)d_in[15];
    const float* Wl2 = (const float*)d_in[16];
    const float* bl2 = (const float*)d_in[17];
    float* out = (float*)d_out;

    void *p_aggb_, *p_hb1_, *p_hb2_, *p_xb_, *p_wb_, *p_h3_, *p_gate_;
    cudaGetSymbolAddress(&p_aggb_, d_aggb);
    cudaGetSymbolAddress(&p_hb1_, d_hb1);
    cudaGetSymbolAddress(&p_hb2_, d_hb2);
    cudaGetSymbolAddress(&p_xb_, d_xb);
    cudaGetSymbolAddress(&p_wb_, d_wb);
    cudaGetSymbolAddress(&p_h3_, d_h3);
    cudaGetSymbolAddress(&p_gate_, d_gate);
    __nv_bfloat16* p_aggb = (__nv_bfloat16*)p_aggb_;
    __nv_bfloat16* p_hb1 = (__nv_bfloat16*)p_hb1_;
    __nv_bfloat16* p_hb2 = (__nv_bfloat16*)p_hb2_;
    __nv_bfloat16* p_xb = (__nv_bfloat16*)p_xb_;
    __nv_bfloat16* p_wb = (__nv_bfloat16*)p_wb_;
    float* p_h3 = (float*)p_h3_;
    float* p_gate = (float*)p_gate_;

    const int eblocks = (E_EDGES + 255) / 256;

    // CSR build
    zero_deg_kernel<<<(N_NODES + 255) / 256, 256>>>();
    hist_kernel<<<eblocks, 256>>>(ei);
    scan_phaseA<<<NSB, 256>>>();
    scan_phaseB<<<1, 256>>>();
    scan_phaseC<<<NSB, 256>>>();
    fill_kernel<<<eblocks, 256>>>(ei);

    // converts
    convert_x_kernel<<<(N_NODES * F_IN / 4 + 255) / 256, 256>>>(x);
    convert_w_kernel<<<(W_TOTAL + 255) / 256, 256>>>(W1l, W1r, W2l, W2r, W3l, W3r);

    dim3 gemm_grid((N_NODES + 127) / 128, HID / 64);

    // layer 1: gather bf16 x -> aggb; bf16 GEMM -> hb1 (bf16 only)
    aggregate_bf16_k128<<<N_NODES, 64>>>(p_xb, p_aggb);
    sage_linear_bf16<<<gemm_grid, 256>>>(p_aggb, p_xb, p_wb + OFF_W1L, p_wb + OFF_W1R,
                                         b1l, nullptr, p_hb1, N_NODES, F_IN);
    // layer 2: gather hb1 -> aggb; GEMM -> hb2 (bf16 only)
    aggregate_bf16_k256<<<N_NODES, 64>>>(p_hb1, p_aggb);
    sage_linear_bf16<<<gemm_grid, 256>>>(p_aggb, p_hb1, p_wb + OFF_W2L, p_wb + OFF_W2R,
                                         b2l, nullptr, p_hb2, N_NODES, HID);
    // layer 3: gather hb2 -> aggb; GEMM -> h3 (fp32 only, feeds gate/pool)
    aggregate_bf16_k256<<<N_NODES, 64>>>(p_hb2, p_aggb);
    sage_linear_bf16<<<gemm_grid, 256>>>(p_aggb, p_hb2, p_wb + OFF_W3L, p_wb + OFF_W3R,
                                         b3l, p_h3, nullptr, N_NODES, HID);

    // pooling + head
    gate_kernel<<<256, 256>>>(p_h3, Wg, bg, p_gate);
    batch_bounds_kernel<<<1, NB + 1>>>(batch);
    pool_stats_kernel<<<NB, 256>>>(p_gate);
    pool_acc_kernel<<<dim3(NB, PSPLIT), 64>>>(p_h3, p_gate);
    head_kernel<<<NB, HID>>>(Wl1, bl1, Wl2, bl2, out);
}